// round 1
// baseline (speedup 1.0000x reference)
#include <cuda_runtime.h>
#include <math.h>

#define BB 4
#define NN 2048
#define DIMM 512
#define TT 16
#define HH 8
#define DHH 64
#define ROWS (BB*NN)   // 8192

// ---------------- scratch (static device globals: no allocs) ----------------
__device__ float g_xn[ROWS*DIMM];              // layernorm output [8192,512]
__device__ float g_q[BB*HH*NN*DHH];            // [b,h,n,64]
__device__ float g_k[BB*HH*NN*DHH];
__device__ float g_v[BB*HH*NN*DHH];
__device__ float g_attn[ROWS*DIMM];            // attention out [b,n,h*64] = [8192,512]

// ---------------- LayerNorm ----------------
__global__ void __launch_bounds__(256) ln_kernel(const float* __restrict__ x,
                                                 const float* __restrict__ gamma,
                                                 const float* __restrict__ beta,
                                                 float* __restrict__ xn)
{
    int row = blockIdx.x;              // 8192 rows
    int t = threadIdx.x;               // 256 threads, 2 floats each
    const float2* xr = (const float2*)(x + (size_t)row * DIMM);
    float2 v = xr[t];
    float s  = v.x + v.y;
    float ss = v.x*v.x + v.y*v.y;
    #pragma unroll
    for (int o = 16; o > 0; o >>= 1) {
        s  += __shfl_xor_sync(0xffffffffu, s,  o);
        ss += __shfl_xor_sync(0xffffffffu, ss, o);
    }
    __shared__ float ws[8], wss[8];
    int w = t >> 5, lane = t & 31;
    if (lane == 0) { ws[w] = s; wss[w] = ss; }
    __syncthreads();
    if (w == 0) {
        s  = (lane < 8) ? ws[lane]  : 0.f;
        ss = (lane < 8) ? wss[lane] : 0.f;
        #pragma unroll
        for (int o = 4; o > 0; o >>= 1) {
            s  += __shfl_xor_sync(0xffffffffu, s,  o);
            ss += __shfl_xor_sync(0xffffffffu, ss, o);
        }
        if (lane == 0) { ws[0] = s; wss[0] = ss; }
    }
    __syncthreads();
    s = ws[0]; ss = wss[0];
    float mu  = s  * (1.0f / DIMM);
    float var = ss * (1.0f / DIMM) - mu * mu;
    float inv = rsqrtf(var + 1e-5f);
    float2 g = ((const float2*)gamma)[t];
    float2 be = ((const float2*)beta)[t];
    float2 o;
    o.x = (v.x - mu) * inv * g.x + be.x;
    o.y = (v.y - mu) * inv * g.y + be.y;
    ((float2*)(xn + (size_t)row * DIMM))[t] = o;
}

// ---------------- 128x128 tiled SGEMM, optional QKV scatter epilogue ----------------
template<bool SCATTER>
__global__ void __launch_bounds__(256) sgemm128(const float* __restrict__ A,
                                                const float* __restrict__ B,
                                                float* __restrict__ C,
                                                int M, int N, int K,
                                                float* __restrict__ qo,
                                                float* __restrict__ ko,
                                                float* __restrict__ vo)
{
    __shared__ float sA[16 * 128];   // A^T tile: sA[k][m]
    __shared__ float sB[16 * 128];   // B tile:   sB[k][n]
    int tid = threadIdx.x;
    int tx = tid & 15, ty = tid >> 4;
    int n0 = blockIdx.x * 128, m0 = blockIdx.y * 128;

    float acc[8][8];
    #pragma unroll
    for (int i = 0; i < 8; i++)
        #pragma unroll
        for (int j = 0; j < 8; j++) acc[i][j] = 0.f;

    for (int kt = 0; kt < K; kt += 16) {
        #pragma unroll
        for (int l = 0; l < 2; l++) {
            int u = tid + l * 256;
            int row = u >> 2, kc = (u & 3) << 2;
            float4 av = *(const float4*)(A + (size_t)(m0 + row) * K + kt + kc);
            sA[(kc + 0) * 128 + row] = av.x;
            sA[(kc + 1) * 128 + row] = av.y;
            sA[(kc + 2) * 128 + row] = av.z;
            sA[(kc + 3) * 128 + row] = av.w;
        }
        #pragma unroll
        for (int l = 0; l < 2; l++) {
            int u = tid + l * 256;
            int kr = u >> 5, nc = (u & 31) << 2;
            *(float4*)(sB + kr * 128 + nc) =
                *(const float4*)(B + (size_t)(kt + kr) * N + n0 + nc);
        }
        __syncthreads();
        #pragma unroll
        for (int kk = 0; kk < 16; kk++) {
            float4 a0 = *(float4*)(sA + kk * 128 + ty * 8);
            float4 a1 = *(float4*)(sA + kk * 128 + ty * 8 + 4);
            float4 b0 = *(float4*)(sB + kk * 128 + tx * 8);
            float4 b1 = *(float4*)(sB + kk * 128 + tx * 8 + 4);
            float avv[8] = {a0.x, a0.y, a0.z, a0.w, a1.x, a1.y, a1.z, a1.w};
            float bvv[8] = {b0.x, b0.y, b0.z, b0.w, b1.x, b1.y, b1.z, b1.w};
            #pragma unroll
            for (int i = 0; i < 8; i++)
                #pragma unroll
                for (int j = 0; j < 8; j++)
                    acc[i][j] += avv[i] * bvv[j];
        }
        __syncthreads();
    }

    if (SCATTER) {
        // C col c in [0,1536): part = c/512 (q/k/v), h = (c%512)/64, d = c%64
        // row r = b*2048 + n; dst layout [b,h,n,64]
        #pragma unroll
        for (int i = 0; i < 8; i++) {
            int r = m0 + ty * 8 + i;
            int b = r >> 11, n = r & 2047;
            #pragma unroll
            for (int j = 0; j < 8; j++) {
                int cc = n0 + tx * 8 + j;
                int part = cc >> 9;
                int h = (cc >> 6) & 7;
                int d = cc & 63;
                float* dst = (part == 0) ? qo : ((part == 1) ? ko : vo);
                dst[(((size_t)(b * HH + h)) * NN + n) * DHH + d] = acc[i][j];
            }
        }
    } else {
        #pragma unroll
        for (int i = 0; i < 8; i++) {
            int r = m0 + ty * 8 + i;
            #pragma unroll
            for (int j = 0; j < 8; j++) {
                int cc = n0 + tx * 8 + j;
                C[(size_t)r * N + cc] = acc[i][j];
            }
        }
    }
}

// ---------------- Flash attention with per-tile scalar decay ----------------
// grid = B*H*16 blocks; block 256 threads; Q tile 128 rows, K/V tiles 128 rows.
// decay is constant per (q-tile, k-tile): timepoint = token/128.
#define SQ_STRIDE 132   // transposed [64][132] : sQ[d][n]
#define SV_STRIDE 68    // [128][68] : sV[n][d]
#define SS_STRIDE 132   // [128][132]: P tile
#define FLASH_SMEM ((64*SQ_STRIDE + 64*SQ_STRIDE + 128*SV_STRIDE + 128*SS_STRIDE) * 4)

__global__ void __launch_bounds__(256) flash_kernel(const float* __restrict__ Qg,
                                                    const float* __restrict__ Kg,
                                                    const float* __restrict__ Vg,
                                                    const float* __restrict__ Rg,
                                                    const float* __restrict__ avec,
                                                    const float* __restrict__ cvec,
                                                    float* __restrict__ Og)
{
    extern __shared__ float sm[];
    float* sQ = sm;                        // [64][132] transposed
    float* sK = sQ + 64 * SQ_STRIDE;       // [64][132] transposed
    float* sV = sK + 64 * SQ_STRIDE;       // [128][68]
    float* sS = sV + 128 * SV_STRIDE;      // [128][132]

    int tid = threadIdx.x;
    int tx = tid & 15, ty = tid >> 4;
    int bid = blockIdx.x;
    int qt = bid & 15;
    int h  = (bid >> 4) & 7;
    int b  = bid >> 7;
    int bh = b * HH + h;

    const float scale = 0.125f;  // 64^-0.5
    float aa = fabsf(avec[h]);
    float ca = fabsf(cvec[h]);

    // load Q tile transposed (global coalesced over d)
    const float* Qb = Qg + ((size_t)bh * NN + qt * 128) * DHH;
    for (int idx = tid; idx < 128 * 64; idx += 256) {
        int n = idx >> 6, d = idx & 63;
        sQ[d * SQ_STRIDE + n] = Qb[idx];
    }

    float mrow[8], lrow[8], oacc[8][4];
    #pragma unroll
    for (int i = 0; i < 8; i++) {
        mrow[i] = -1e30f;
        lrow[i] = 0.f;
        #pragma unroll
        for (int j = 0; j < 4; j++) oacc[i][j] = 0.f;
    }

    for (int jt = 0; jt < 16; jt++) {
        __syncthreads();  // previous O-gemm done reading sK/sV/sS
        const float* Kb = Kg + ((size_t)bh * NN + jt * 128) * DHH;
        const float* Vb = Vg + ((size_t)bh * NN + jt * 128) * DHH;
        for (int idx = tid; idx < 128 * 64; idx += 256) {
            int n = idx >> 6, d = idx & 63;
            sK[d * SQ_STRIDE + n] = Kb[idx];
            sV[n * SV_STRIDE + d] = Vb[idx];
        }
        __syncthreads();

        float rbij = Rg[((size_t)b * TT + qt) * TT + jt];
        float decay = 1.f / (1.f + __expf(aa * rbij - ca));

        // S = Q @ K^T, 128x128, K=64
        float sacc[8][8];
        #pragma unroll
        for (int i = 0; i < 8; i++)
            #pragma unroll
            for (int j = 0; j < 8; j++) sacc[i][j] = 0.f;

        #pragma unroll 8
        for (int kk = 0; kk < 64; kk++) {
            float4 a0 = *(float4*)(sQ + kk * SQ_STRIDE + ty * 8);
            float4 a1 = *(float4*)(sQ + kk * SQ_STRIDE + ty * 8 + 4);
            float4 b0 = *(float4*)(sK + kk * SQ_STRIDE + tx * 8);
            float4 b1 = *(float4*)(sK + kk * SQ_STRIDE + tx * 8 + 4);
            float avv[8] = {a0.x, a0.y, a0.z, a0.w, a1.x, a1.y, a1.z, a1.w};
            float bvv[8] = {b0.x, b0.y, b0.z, b0.w, b1.x, b1.y, b1.z, b1.w};
            #pragma unroll
            for (int i = 0; i < 8; i++)
                #pragma unroll
                for (int j = 0; j < 8; j++)
                    sacc[i][j] += avv[i] * bvv[j];
        }

        // relu * scale * decay, online softmax update, write P to sS
        #pragma unroll
        for (int i = 0; i < 8; i++) {
            float sv[8];
            float mx = 0.f;   // scores are >= 0 after relu
            #pragma unroll
            for (int j = 0; j < 8; j++) {
                sv[j] = fmaxf(sacc[i][j] * scale, 0.f) * decay;
                mx = fmaxf(mx, sv[j]);
            }
            #pragma unroll
            for (int o = 8; o > 0; o >>= 1)
                mx = fmaxf(mx, __shfl_xor_sync(0xffffffffu, mx, o));
            float mn = fmaxf(mrow[i], mx);
            float ef = __expf(mrow[i] - mn);
            mrow[i] = mn;
            float rs = 0.f;
            #pragma unroll
            for (int j = 0; j < 8; j++) {
                float p = __expf(sv[j] - mn);
                sS[(ty * 8 + i) * SS_STRIDE + tx * 8 + j] = p;
                rs += p;
            }
            #pragma unroll
            for (int o = 8; o > 0; o >>= 1)
                rs += __shfl_xor_sync(0xffffffffu, rs, o);
            lrow[i] = lrow[i] * ef + rs;
            #pragma unroll
            for (int j = 0; j < 4; j++) oacc[i][j] *= ef;
        }
        __syncthreads();

        // O += P @ V : 128x64, K=128. thread tile 8 rows x 4 cols
        #pragma unroll 4
        for (int kk = 0; kk < 128; kk++) {
            float4 bv = *(float4*)(sV + kk * SV_STRIDE + tx * 4);
            #pragma unroll
            for (int i = 0; i < 8; i++) {
                float aval = sS[(ty * 8 + i) * SS_STRIDE + kk];
                oacc[i][0] += aval * bv.x;
                oacc[i][1] += aval * bv.y;
                oacc[i][2] += aval * bv.z;
                oacc[i][3] += aval * bv.w;
            }
        }
    }

    // normalize + write to [b, n, h*64+d] layout (== [8192, 512] row-major)
    float* Ob = Og + ((size_t)b * NN + qt * 128) * DIMM + h * DHH;
    #pragma unroll
    for (int i = 0; i < 8; i++) {
        float rinv = 1.f / lrow[i];
        #pragma unroll
        for (int j = 0; j < 4; j++)
            Ob[(size_t)(ty * 8 + i) * DIMM + tx * 4 + j] = oacc[i][j] * rinv;
    }
}

// ---------------- launch ----------------
extern "C" void kernel_launch(void* const* d_in, const int* in_sizes, int n_in,
                              void* d_out, int out_size)
{
    const float* x     = (const float*)d_in[0];
    const float* R     = (const float*)d_in[1];
    const float* gamma = (const float*)d_in[2];
    const float* beta  = (const float*)d_in[3];
    const float* Wqkv  = (const float*)d_in[4];
    const float* Wout  = (const float*)d_in[5];
    const float* av    = (const float*)d_in[6];
    const float* cv    = (const float*)d_in[7];
    float* out = (float*)d_out;

    float *xn, *q, *k, *v, *attn;
    cudaGetSymbolAddress((void**)&xn,   g_xn);
    cudaGetSymbolAddress((void**)&q,    g_q);
    cudaGetSymbolAddress((void**)&k,    g_k);
    cudaGetSymbolAddress((void**)&v,    g_v);
    cudaGetSymbolAddress((void**)&attn, g_attn);

    // 1) LayerNorm
    ln_kernel<<<ROWS, 256>>>(x, gamma, beta, xn);

    // 2) QKV projection: [8192,512] @ [512,1536], scatter into q/k/v [b,h,n,64]
    sgemm128<true><<<dim3(1536 / 128, ROWS / 128), 256>>>(
        xn, Wqkv, nullptr, ROWS, 3 * HH * DHH, DIMM, q, k, v);

    // 3) Flash attention with time-decay mask
    cudaFuncSetAttribute(flash_kernel,
                         cudaFuncAttributeMaxDynamicSharedMemorySize, FLASH_SMEM);
    flash_kernel<<<BB * HH * 16, 256, FLASH_SMEM>>>(q, k, v, R, av, cv, attn);

    // 4) Output projection: [8192,512] @ [512,512] -> d_out
    sgemm128<false><<<dim3(DIMM / 128, ROWS / 128), 256>>>(
        attn, Wout, out, ROWS, DIMM, DIMM, nullptr, nullptr, nullptr);
}

// round 3
// speedup vs baseline: 3.2658x; 3.2658x over previous
#include <cuda_runtime.h>
#include <cuda_bf16.h>
#include <cstdint>
#include <math.h>

#define BB 4
#define NN 2048
#define DIMM 512
#define TT 16
#define HH 8
#define DHH 64
#define ROWS (BB*NN)          // 8192
#define QKVN (3*HH*DHH)       // 1536
#define HDSZ (BB*HH*NN*DHH)

typedef __nv_bfloat16 bf16;

// ---------------- scratch (static device globals) ----------------
__device__ bf16 g_xnh[ROWS*DIMM], g_xnl[ROWS*DIMM];
__device__ bf16 g_wqh[QKVN*DIMM], g_wql[QKVN*DIMM];   // W_qkv^T [1536][512]
__device__ bf16 g_woh[DIMM*DIMM], g_wol[DIMM*DIMM];   // W_out^T [512][512]
__device__ bf16 g_qh[HDSZ], g_ql[HDSZ];
__device__ bf16 g_kh[HDSZ], g_kl[HDSZ];
__device__ bf16 g_vh[HDSZ], g_vl[HDSZ];
__device__ bf16 g_ah[ROWS*DIMM], g_al[ROWS*DIMM];     // attention out hi/lo

// ---------------- helpers ----------------
__device__ __forceinline__ uint32_t swz(uint32_t o) { return o ^ ((o >> 3) & 0x70u); }

__device__ __forceinline__ uint32_t smem_u32(const void* p) {
    uint32_t a;
    asm("{ .reg .u64 t; cvta.to.shared.u64 t, %1; cvt.u32.u64 %0, t; }" : "=r"(a) : "l"(p));
    return a;
}

__device__ __forceinline__ uint32_t pack2(float lo, float hi) {
    uint32_t r;
    asm("cvt.rn.bf16x2.f32 %0, %1, %2;" : "=r"(r) : "f"(hi), "f"(lo));
    return r;
}
__device__ __forceinline__ void split_pack(float f0, float f1, uint32_t& hp, uint32_t& lp) {
    float h0 = __bfloat162float(__float2bfloat16(f0));
    float h1 = __bfloat162float(__float2bfloat16(f1));
    hp = pack2(h0, h1);
    lp = pack2(f0 - h0, f1 - h1);
}

__device__ __forceinline__ void ldsm_x4(uint32_t* r, uint32_t addr) {
    asm volatile("ldmatrix.sync.aligned.m8n8.x4.shared.b16 {%0,%1,%2,%3}, [%4];"
        : "=r"(r[0]), "=r"(r[1]), "=r"(r[2]), "=r"(r[3]) : "r"(addr));
}
__device__ __forceinline__ void ldsm_x4t(uint32_t* r, uint32_t addr) {
    asm volatile("ldmatrix.sync.aligned.m8n8.x4.trans.shared.b16 {%0,%1,%2,%3}, [%4];"
        : "=r"(r[0]), "=r"(r[1]), "=r"(r[2]), "=r"(r[3]) : "r"(addr));
}
__device__ __forceinline__ void mma16816(float* c, const uint32_t* a, const uint32_t* b) {
    asm volatile("mma.sync.aligned.m16n8k16.row.col.f32.bf16.bf16.f32 "
        "{%0,%1,%2,%3}, {%4,%5,%6,%7}, {%8,%9}, {%0,%1,%2,%3};"
        : "+f"(c[0]), "+f"(c[1]), "+f"(c[2]), "+f"(c[3])
        : "r"(a[0]), "r"(a[1]), "r"(a[2]), "r"(a[3]), "r"(b[0]), "r"(b[1]));
}
__device__ __forceinline__ void cp16(uint32_t dst, const void* src) {
    asm volatile("cp.async.cg.shared.global [%0], [%1], 16;" :: "r"(dst), "l"(src) : "memory");
}
#define CP_COMMIT() asm volatile("cp.async.commit_group;" ::: "memory")
#define CP_WAIT1()  asm volatile("cp.async.wait_group 1;" ::: "memory")
#define CP_WAIT0()  asm volatile("cp.async.wait_group 0;" ::: "memory")

// ---------------- LayerNorm -> bf16 hi/lo ----------------
__global__ void __launch_bounds__(256) ln_kernel(const float* __restrict__ x,
                                                 const float* __restrict__ gamma,
                                                 const float* __restrict__ beta,
                                                 bf16* __restrict__ xnh,
                                                 bf16* __restrict__ xnl)
{
    int row = blockIdx.x;
    int t = threadIdx.x;
    const float2* xr = (const float2*)(x + (size_t)row * DIMM);
    float2 v = xr[t];
    float s = v.x + v.y, ss = v.x*v.x + v.y*v.y;
    #pragma unroll
    for (int o = 16; o > 0; o >>= 1) {
        s  += __shfl_xor_sync(0xffffffffu, s,  o);
        ss += __shfl_xor_sync(0xffffffffu, ss, o);
    }
    __shared__ float ws[8], wss[8];
    int w = t >> 5, lane = t & 31;
    if (lane == 0) { ws[w] = s; wss[w] = ss; }
    __syncthreads();
    if (w == 0) {
        s  = (lane < 8) ? ws[lane]  : 0.f;
        ss = (lane < 8) ? wss[lane] : 0.f;
        #pragma unroll
        for (int o = 4; o > 0; o >>= 1) {
            s  += __shfl_xor_sync(0xffffffffu, s,  o);
            ss += __shfl_xor_sync(0xffffffffu, ss, o);
        }
        if (lane == 0) { ws[0] = s; wss[0] = ss; }
    }
    __syncthreads();
    s = ws[0]; ss = wss[0];
    float mu  = s * (1.0f / DIMM);
    float var = ss * (1.0f / DIMM) - mu * mu;
    float inv = rsqrtf(var + 1e-5f);
    float2 g = ((const float2*)gamma)[t];
    float2 be = ((const float2*)beta)[t];
    float o0 = (v.x - mu) * inv * g.x + be.x;
    float o1 = (v.y - mu) * inv * g.y + be.y;
    uint32_t hp, lp;
    split_pack(o0, o1, hp, lp);
    ((uint32_t*)(xnh + (size_t)row * DIMM))[t] = hp;
    ((uint32_t*)(xnl + (size_t)row * DIMM))[t] = lp;
}

// ---------------- weight transpose + split ----------------
__global__ void __launch_bounds__(256) wconv_kernel(const float* __restrict__ Wq,
                                                    const float* __restrict__ Wo)
{
    int i = blockIdx.x * 256 + threadIdx.x;
    const int T1 = QKVN * DIMM;
    const int T2 = DIMM * DIMM;
    if (i < T1) {
        int n = i >> 9, k = i & 511;
        float v = Wq[(size_t)k * QKVN + n];
        bf16 h = __float2bfloat16(v);
        g_wqh[i] = h;
        g_wql[i] = __float2bfloat16(v - __bfloat162float(h));
    } else if (i < T1 + T2) {
        int j = i - T1;
        int n = j >> 9, k = j & 511;
        float v = Wo[(size_t)k * DIMM + n];
        bf16 h = __float2bfloat16(v);
        g_woh[j] = h;
        g_wol[j] = __float2bfloat16(v - __bfloat162float(h));
    }
}

// ---------------- HMMA GEMM: C[M,N] = A[M,K] @ B[N,K]^T, 3-term hi/lo ----------------
// CTA 128x128, 8 warps (2x4), K chunk 64, 2-stage cp.async pipeline.
#define GSTAGE 65536
#define GEMM_SMEM (2*GSTAGE)

template<bool SCATTER>
__global__ void __launch_bounds__(256)
mma_gemm(const bf16* __restrict__ Ah, const bf16* __restrict__ Al,
         const bf16* __restrict__ Bh, const bf16* __restrict__ Bl,
         float* __restrict__ C, int Ncols, int K,
         bf16* qh, bf16* ql, bf16* kh, bf16* kl, bf16* vh, bf16* vl)
{
    extern __shared__ char smc[];
    uint32_t sb = smem_u32(smc);
    int tid = threadIdx.x, lane = tid & 31, wid = tid >> 5;
    int n0 = blockIdx.x * 128, m0 = blockIdx.y * 128;
    int m0w = (wid >> 2) * 64, n0w = (wid & 3) * 32;

    const bf16* srcs[4] = {Ah + (size_t)m0 * K, Al + (size_t)m0 * K,
                           Bh + (size_t)n0 * K, Bl + (size_t)n0 * K};

    auto load_chunk = [&](int kc, int st) {
        uint32_t base = sb + st * GSTAGE;
        int kofs = kc * 64;
        #pragma unroll
        for (int t = 0; t < 4; t++) {
            const bf16* s = srcs[t] + kofs;
            #pragma unroll
            for (int i = 0; i < 4; i++) {
                int u = tid + i * 256;
                int row = u >> 3, g = u & 7;
                cp16(base + t * 16384 + swz(row * 128 + g * 16),
                     s + (size_t)row * K + g * 8);
            }
        }
        CP_COMMIT();
    };

    float acc[4][4][4];
    #pragma unroll
    for (int a = 0; a < 4; a++)
        #pragma unroll
        for (int b = 0; b < 4; b++)
            #pragma unroll
            for (int c = 0; c < 4; c++) acc[a][b][c] = 0.f;

    load_chunk(0, 0);
    int nch = K >> 6;
    for (int kc = 0; kc < nch; kc++) {
        if (kc + 1 < nch) { load_chunk(kc + 1, (kc + 1) & 1); CP_WAIT1(); }
        else              { CP_WAIT0(); }
        __syncthreads();
        uint32_t bAh = sb + (kc & 1) * GSTAGE;
        uint32_t bAl = bAh + 16384, bBh = bAh + 32768, bBl = bAh + 49152;
        #pragma unroll
        for (int kt = 0; kt < 4; kt++) {
            uint32_t afh[4][4], afl[4][4];
            #pragma unroll
            for (int mt = 0; mt < 4; mt++) {
                uint32_t byte = swz((m0w + mt * 16 + (lane & 15)) * 128 +
                                    kt * 32 + (lane >> 4) * 16);
                ldsm_x4(afh[mt], bAh + byte);
                ldsm_x4(afl[mt], bAl + byte);
            }
            uint32_t bfh[2][4], bfl[2][4];
            #pragma unroll
            for (int p = 0; p < 2; p++) {
                uint32_t byte = swz((n0w + p * 16 + (lane & 7) + ((lane >> 4) << 3)) * 128 +
                                    kt * 32 + ((lane >> 3) & 1) * 16);
                ldsm_x4(bfh[p], bBh + byte);
                ldsm_x4(bfl[p], bBl + byte);
            }
            #pragma unroll
            for (int mt = 0; mt < 4; mt++)
                #pragma unroll
                for (int nt = 0; nt < 4; nt++) {
                    const uint32_t* B2h = &bfh[nt >> 1][(nt & 1) * 2];
                    const uint32_t* B2l = &bfl[nt >> 1][(nt & 1) * 2];
                    mma16816(acc[mt][nt], afh[mt], B2h);
                    mma16816(acc[mt][nt], afh[mt], B2l);
                    mma16816(acc[mt][nt], afl[mt], B2h);
                }
        }
        __syncthreads();
    }

    // epilogue
    int rbase = m0 + m0w + (lane >> 2);
    int cbase = n0 + n0w + 2 * (lane & 3);
    #pragma unroll
    for (int mt = 0; mt < 4; mt++) {
        #pragma unroll
        for (int nt = 0; nt < 4; nt++) {
            #pragma unroll
            for (int half = 0; half < 2; half++) {
                int r = rbase + mt * 16 + half * 8;
                int cc = cbase + nt * 8;
                float f0 = acc[mt][nt][half * 2], f1 = acc[mt][nt][half * 2 + 1];
                if (SCATTER) {
                    uint32_t hp, lp;
                    split_pack(f0, f1, hp, lp);
                    int b = r >> 11, n = r & 2047;
                    int part = cc >> 9, h = (cc >> 6) & 7, d = cc & 63;
                    size_t idx = (((size_t)(b * HH + h)) * NN + n) * DHH + d;
                    bf16 *dh, *dl;
                    if (part == 0)      { dh = qh; dl = ql; }
                    else if (part == 1) { dh = kh; dl = kl; }
                    else                { dh = vh; dl = vl; }
                    *(uint32_t*)(dh + idx) = hp;
                    *(uint32_t*)(dl + idx) = lp;
                } else {
                    float2 o2; o2.x = f0; o2.y = f1;
                    *(float2*)(C + (size_t)r * Ncols + cc) = o2;
                }
            }
        }
    }
}

// ---------------- HMMA flash attention ----------------
// 8 warps; warp w owns q-rows [w*16, w*16+16). S in regs, no max-rescale
// (relu bounds logits), O accumulates in regs across all 16 KV tiles.
#define FQ 0
#define FKV 32768
#define FSTAGE 65536
#define FLASH_SMEM (FKV + 2*FSTAGE)   // 163840

__global__ void __launch_bounds__(256)
flash_mma(const bf16* __restrict__ qh, const bf16* __restrict__ ql,
          const bf16* __restrict__ kh, const bf16* __restrict__ kl,
          const bf16* __restrict__ vh, const bf16* __restrict__ vl,
          const float* __restrict__ Rg,
          const float* __restrict__ avec, const float* __restrict__ cvec,
          bf16* __restrict__ ah, bf16* __restrict__ al)
{
    extern __shared__ char smc[];
    uint32_t sb = smem_u32(smc);
    int tid = threadIdx.x, lane = tid & 31, wid = tid >> 5;
    int bid = blockIdx.x;
    int qt = bid & 15, h = (bid >> 4) & 7, b = bid >> 7;
    int bh = b * HH + h;

    float aa = fabsf(avec[h]);
    float ca = fabsf(cvec[h]);

    auto load_kv = [&](int jt, int st) {
        size_t o = ((size_t)bh * NN + jt * 128) * DHH;
        const bf16* s4[4] = {kh + o, kl + o, vh + o, vl + o};
        uint32_t base = sb + FKV + st * FSTAGE;
        #pragma unroll
        for (int t = 0; t < 4; t++) {
            #pragma unroll
            for (int i = 0; i < 4; i++) {
                int u = tid + i * 256;
                int row = u >> 3, g = u & 7;
                cp16(base + t * 16384 + swz(row * 128 + g * 16),
                     s4[t] + (size_t)row * DHH + g * 8);
            }
        }
        CP_COMMIT();
    };

    // Q tiles (persistent) — issued before kv0, committed together in load_kv(0,0)
    {
        size_t qo = ((size_t)bh * NN + qt * 128) * DHH;
        const bf16* s2[2] = {qh + qo, ql + qo};
        #pragma unroll
        for (int t = 0; t < 2; t++) {
            #pragma unroll
            for (int i = 0; i < 4; i++) {
                int u = tid + i * 256;
                int row = u >> 3, g = u & 7;
                cp16(sb + FQ + t * 16384 + swz(row * 128 + g * 16),
                     s2[t] + (size_t)row * DHH + g * 8);
            }
        }
    }
    load_kv(0, 0);

    float oacc[8][4];
    #pragma unroll
    for (int i = 0; i < 8; i++)
        #pragma unroll
        for (int j = 0; j < 4; j++) oacc[i][j] = 0.f;
    float rsum_lo = 0.f, rsum_hi = 0.f;

    for (int jt = 0; jt < 16; jt++) {
        if (jt + 1 < 16) { load_kv(jt + 1, (jt + 1) & 1); CP_WAIT1(); }
        else             { CP_WAIT0(); }
        __syncthreads();
        uint32_t bKh = sb + FKV + (jt & 1) * FSTAGE;
        uint32_t bKl = bKh + 16384, bVh = bKh + 32768, bVl = bKh + 49152;

        // ---- S = Q @ K^T (3-term), S tile 16 x 128 per warp
        float sacc[16][4];
        #pragma unroll
        for (int i = 0; i < 16; i++)
            #pragma unroll
            for (int j = 0; j < 4; j++) sacc[i][j] = 0.f;

        #pragma unroll
        for (int kt = 0; kt < 4; kt++) {
            uint32_t qa[4], qal[4];
            uint32_t abyte = swz((wid * 16 + (lane & 15)) * 128 +
                                 kt * 32 + (lane >> 4) * 16);
            ldsm_x4(qa,  sb + FQ + abyte);
            ldsm_x4(qal, sb + FQ + 16384 + abyte);
            #pragma unroll
            for (int p = 0; p < 8; p++) {
                uint32_t bbyte = swz((p * 16 + (lane & 7) + ((lane >> 4) << 3)) * 128 +
                                     kt * 32 + ((lane >> 3) & 1) * 16);
                uint32_t kb[4], kbl[4];
                ldsm_x4(kb,  bKh + bbyte);
                ldsm_x4(kbl, bKl + bbyte);
                #pragma unroll
                for (int half = 0; half < 2; half++) {
                    int nt = 2 * p + half;
                    mma16816(sacc[nt], qa,  &kb[half * 2]);
                    mma16816(sacc[nt], qa,  &kbl[half * 2]);
                    mma16816(sacc[nt], qal, &kb[half * 2]);
                }
            }
        }

        // ---- softmax numerator (bounded logits: no max subtraction)
        float rb = Rg[((size_t)b * TT + qt) * TT + jt];
        float decay = 1.f / (1.f + __expf(aa * rb - ca));
        float rlo = 0.f, rhi = 0.f;
        #pragma unroll
        for (int nt = 0; nt < 16; nt++) {
            #pragma unroll
            for (int r = 0; r < 4; r++) {
                float p = __expf(fmaxf(sacc[nt][r] * 0.125f, 0.f) * decay);
                sacc[nt][r] = p;
                if (r < 2) rlo += p; else rhi += p;
            }
        }
        rlo += __shfl_xor_sync(0xffffffffu, rlo, 1);
        rlo += __shfl_xor_sync(0xffffffffu, rlo, 2);
        rhi += __shfl_xor_sync(0xffffffffu, rhi, 1);
        rhi += __shfl_xor_sync(0xffffffffu, rhi, 2);
        rsum_lo += rlo;
        rsum_hi += rhi;

        // ---- O += P @ V : P re-split hi/lo in regs as A operand; V via trans ldmatrix
        #pragma unroll
        for (int kt = 0; kt < 8; kt++) {
            uint32_t pah[4], pal[4];
            split_pack(sacc[2*kt][0],   sacc[2*kt][1],   pah[0], pal[0]);
            split_pack(sacc[2*kt][2],   sacc[2*kt][3],   pah[1], pal[1]);
            split_pack(sacc[2*kt+1][0], sacc[2*kt+1][1], pah[2], pal[2]);
            split_pack(sacc[2*kt+1][2], sacc[2*kt+1][3], pah[3], pal[3]);
            #pragma unroll
            for (int p = 0; p < 4; p++) {
                uint32_t vbyte = swz((kt * 16 + (lane & 7) + ((lane >> 3) & 1) * 8) * 128 +
                                     p * 32 + (lane >> 4) * 16);
                uint32_t vb[4], vbl[4];
                ldsm_x4t(vb,  bVh + vbyte);
                ldsm_x4t(vbl, bVl + vbyte);
                #pragma unroll
                for (int half = 0; half < 2; half++) {
                    int nt = 2 * p + half;
                    mma16816(oacc[nt], pah, &vb[half * 2]);
                    mma16816(oacc[nt], pah, &vbl[half * 2]);
                    mma16816(oacc[nt], pal, &vb[half * 2]);
                }
            }
        }
        __syncthreads();
    }

    // ---- epilogue: normalize, split hi/lo, store
    float inv_lo = 1.f / rsum_lo, inv_hi = 1.f / rsum_hi;
    int r0 = qt * 128 + wid * 16 + (lane >> 2);
    bf16* oh = ah + ((size_t)b * NN + r0) * DIMM + h * DHH;
    bf16* ol = al + ((size_t)b * NN + r0) * DIMM + h * DHH;
    #pragma unroll
    for (int nt = 0; nt < 8; nt++) {
        int c = nt * 8 + 2 * (lane & 3);
        uint32_t hp, lp;
        split_pack(oacc[nt][0] * inv_lo, oacc[nt][1] * inv_lo, hp, lp);
        *(uint32_t*)(oh + c) = hp;
        *(uint32_t*)(ol + c) = lp;
        split_pack(oacc[nt][2] * inv_hi, oacc[nt][3] * inv_hi, hp, lp);
        *(uint32_t*)(oh + (size_t)8 * DIMM + c) = hp;
        *(uint32_t*)(ol + (size_t)8 * DIMM + c) = lp;
    }
}

// ---------------- launch ----------------
extern "C" void kernel_launch(void* const* d_in, const int* in_sizes, int n_in,
                              void* d_out, int out_size)
{
    const float* x     = (const float*)d_in[0];
    const float* R     = (const float*)d_in[1];
    const float* gamma = (const float*)d_in[2];
    const float* beta  = (const float*)d_in[3];
    const float* Wqkv  = (const float*)d_in[4];
    const float* Wout  = (const float*)d_in[5];
    const float* av    = (const float*)d_in[6];
    const float* cv    = (const float*)d_in[7];
    float* out = (float*)d_out;

    bf16 *xnh, *xnl, *wqh, *wql, *woh, *wol;
    bf16 *qh, *ql, *kh, *kl, *vh, *vl, *ah, *al;
    cudaGetSymbolAddress((void**)&xnh, g_xnh); cudaGetSymbolAddress((void**)&xnl, g_xnl);
    cudaGetSymbolAddress((void**)&wqh, g_wqh); cudaGetSymbolAddress((void**)&wql, g_wql);
    cudaGetSymbolAddress((void**)&woh, g_woh); cudaGetSymbolAddress((void**)&wol, g_wol);
    cudaGetSymbolAddress((void**)&qh, g_qh);   cudaGetSymbolAddress((void**)&ql, g_ql);
    cudaGetSymbolAddress((void**)&kh, g_kh);   cudaGetSymbolAddress((void**)&kl, g_kl);
    cudaGetSymbolAddress((void**)&vh, g_vh);   cudaGetSymbolAddress((void**)&vl, g_vl);
    cudaGetSymbolAddress((void**)&ah, g_ah);   cudaGetSymbolAddress((void**)&al, g_al);

    cudaFuncSetAttribute(mma_gemm<true>,  cudaFuncAttributeMaxDynamicSharedMemorySize, GEMM_SMEM);
    cudaFuncSetAttribute(mma_gemm<false>, cudaFuncAttributeMaxDynamicSharedMemorySize, GEMM_SMEM);
    cudaFuncSetAttribute(flash_mma, cudaFuncAttributeMaxDynamicSharedMemorySize, FLASH_SMEM);

    // 1) LayerNorm -> bf16 hi/lo
    ln_kernel<<<ROWS, 256>>>(x, gamma, beta, xnh, xnl);

    // 2) weight transpose + split
    wconv_kernel<<<(QKVN * DIMM + DIMM * DIMM + 255) / 256, 256>>>(Wqkv, Wout);

    // 3) QKV projection, scatter to q/k/v hi/lo
    mma_gemm<true><<<dim3(QKVN / 128, ROWS / 128), 256, GEMM_SMEM>>>(
        xnh, xnl, wqh, wql, nullptr, QKVN, DIMM, qh, ql, kh, kl, vh, vl);

    // 4) flash attention
    flash_mma<<<BB * HH * 16, 256, FLASH_SMEM>>>(qh, ql, kh, kl, vh, vl,
                                                 R, av, cv, ah, al);

    // 5) output projection -> d_out fp32
    mma_gemm<false><<<dim3(DIMM / 128, ROWS / 128), 256, GEMM_SMEM>>>(
        ah, al, woh, wol, out, DIMM, DIMM,
        nullptr, nullptr, nullptr, nullptr, nullptr, nullptr);
}